// round 9
// baseline (speedup 1.0000x reference)
#include <cuda_runtime.h>

#define NN 50000
#define NE 800000
#define H  128
#define NG 512
#define NC 10
#define NB_SCAN 49   // ceil(50000/1024)

// ---------------- device scratch (no allocations allowed) ----------------
__device__ int   g_deg[NN];
__device__ float g_inv[NN];
__device__ int   g_rowtmp[NN];
__device__ int   g_row[NN + 1];
__device__ int   g_cur[NN];
__device__ int   g_col[NE];
__device__ int   g_bsum[64];
__device__ int   g_boff[64];
__device__ __align__(16) float g_h0[NN * H];
__device__ __align__(16) float g_h1[NN * H];
__device__ __align__(16) float g_agg[NN * H];
__device__ float g_gate[NN];
__device__ int   g_gstart[NG + 1];
__device__ __align__(16) float g_pooled[NG * H];
__device__ int   g_i64flag;   // 1 if edge_index/batch are int64, 0 if int32

// Buffer selector resolved IN DEVICE CODE ONLY (host never touches symbols).
#define SEL_AGG 0
#define SEL_H0  1
#define SEL_H1  2
__device__ __forceinline__ float* buf_ptr(int sel) {
    return (sel == SEL_AGG) ? g_agg : (sel == SEL_H0) ? g_h0 : g_h1;
}

// dtype-dispatching index reads (JAX default x64-disabled -> int32 likely)
__device__ __forceinline__ int idx_at(const void* p, long long i) {
    if (g_i64flag) return (int)((const long long*)p)[i];
    return ((const int*)p)[i];
}

// ---------------- dtype probe: int64 data has all-zero high words ----------
__global__ void k_dtype(const void* ei) {
    const int* w = (const int*)ei;
    int t = threadIdx.x;                       // 32 threads
    long long k = (long long)t * (NE / 32) + 11;   // element index, < NE
    // odd int32 word: high half of int64 element k, or a real id if int32 data.
    // Safe under both dtypes: word index 2k+1 < 2*NE <= total int32 words.
    unsigned any = __ballot_sync(0xffffffffu, w[2 * k + 1] != 0);
    if (t == 0) g_i64flag = (any == 0) ? 1 : 0;
}

// ---------------- CSR build ----------------
__global__ void k_zero() {
    int i = blockIdx.x * blockDim.x + threadIdx.x;
    if (i < NN) { g_deg[i] = 0; g_cur[i] = 0; }
}

__global__ void k_count(const void* __restrict__ ei) {
    int e = blockIdx.x * blockDim.x + threadIdx.x;
    if (e < NE) {
        int d = idx_at(ei, (long long)NE + e);   // dst row
        if (d >= 0 && d < NN) atomicAdd(&g_deg[d], 1);
    }
}

__global__ void k_scan1() {
    __shared__ int s[1024];
    int tid = threadIdx.x;
    int i = blockIdx.x * 1024 + tid;
    int v = (i < NN) ? g_deg[i] : 0;
    s[tid] = v;
    __syncthreads();
    for (int off = 1; off < 1024; off <<= 1) {
        int t = (tid >= off) ? s[tid - off] : 0;
        __syncthreads();
        s[tid] += t;
        __syncthreads();
    }
    if (i < NN) g_rowtmp[i] = s[tid] - v;   // exclusive within block
    if (tid == 1023) g_bsum[blockIdx.x] = s[1023];
}

__global__ void k_scan2() {
    __shared__ int s[64];
    int tid = threadIdx.x;
    int v = (tid < NB_SCAN) ? g_bsum[tid] : 0;
    s[tid] = v;
    __syncthreads();
    for (int off = 1; off < 64; off <<= 1) {
        int t = (tid >= off) ? s[tid - off] : 0;
        __syncthreads();
        s[tid] += t;
        __syncthreads();
    }
    g_boff[tid] = s[tid] - v;               // exclusive block offsets
}

__global__ void k_scan3() {
    int i = blockIdx.x * blockDim.x + threadIdx.x;
    if (i < NN) {
        g_row[i] = g_rowtmp[i] + g_boff[i >> 10];
        g_inv[i] = 1.0f / fmaxf((float)g_deg[i], 1.0f);
    }
    if (i == 0) g_row[NN] = NE;
}

__global__ void k_fill(const void* __restrict__ ei) {
    int e = blockIdx.x * blockDim.x + threadIdx.x;
    if (e < NE) {
        int src = idx_at(ei, e);
        int dst = idx_at(ei, (long long)NE + e);
        if (dst >= 0 && dst < NN && src >= 0 && src < NN) {
            int pos = g_row[dst] + atomicAdd(&g_cur[dst], 1);
            g_col[pos] = src;
        }
    }
}

// ---------------- mean aggregation: warp per destination node ----------------
__global__ __launch_bounds__(256) void k_agg(const float* __restrict__ x, int in_sel) {
    const float* in = (in_sel < 0) ? x : buf_ptr(in_sel);
    int warp = (blockIdx.x * blockDim.x + threadIdx.x) >> 5;
    int lane = threadIdx.x & 31;
    if (warp >= NN) return;
    int s = g_row[warp], e = g_row[warp + 1];
    float4 acc = make_float4(0.f, 0.f, 0.f, 0.f);
    for (int i = s; i < e; i++) {
        int src = g_col[i];
        float4 v = *reinterpret_cast<const float4*>(in + (size_t)src * H + lane * 4);
        acc.x += v.x; acc.y += v.y; acc.z += v.z; acc.w += v.w;
    }
    float iv = g_inv[warp];
    acc.x *= iv; acc.y *= iv; acc.z *= iv; acc.w *= iv;
    *reinterpret_cast<float4*>(g_agg + (size_t)warp * H + lane * 4) = acc;
}

// ---------------- fused dual GEMM: out = relu(agg@W1 + A2@W2 + b) ----------------
// BM=128, BN=128, BK=8, 256 threads, 8x8 per thread, scalar FFMA.
__global__ __launch_bounds__(256) void k_gemm(
    const float* __restrict__ x, int a2_sel,
    const float* __restrict__ W1, const float* __restrict__ W2,
    const float* __restrict__ bias, int out_sel, int M)
{
    const float* A2 = (a2_sel < 0) ? x : buf_ptr(a2_sel);
    float* out = buf_ptr(out_sel);

    __shared__ __align__(16) float sA[8][132];   // [k][m], padded
    __shared__ __align__(16) float sB[8][132];   // [k][n], padded
    int tid = threadIdx.x;
    int tx = tid & 15, ty = tid >> 4;
    int m0 = blockIdx.x * 128;

    float acc[8][8];
#pragma unroll
    for (int i = 0; i < 8; i++)
#pragma unroll
        for (int j = 0; j < 8; j++) acc[i][j] = 0.f;

    int lm = tid >> 1;            // A-load row within tile (0..127)
    int lh = (tid & 1) * 4;       // A-load col offset (0 or 4)

    for (int pass = 0; pass < 2; pass++) {
        const float* A = pass ? A2 : g_agg;
        const float* W = pass ? W2 : W1;
        for (int kc = 0; kc < 128; kc += 8) {
            float4 va = make_float4(0.f, 0.f, 0.f, 0.f);
            if (m0 + lm < M)
                va = *reinterpret_cast<const float4*>(A + (size_t)(m0 + lm) * 128 + kc + lh);
            float4 vb = *reinterpret_cast<const float4*>(W + (size_t)(kc + (tid >> 5)) * 128 + (tid & 31) * 4);
            __syncthreads();
            sA[lh + 0][lm] = va.x; sA[lh + 1][lm] = va.y;
            sA[lh + 2][lm] = va.z; sA[lh + 3][lm] = va.w;
            {
                int br = tid >> 5;            // 0..7
                int bc = (tid & 31) * 4;      // 0..124
                sB[br][bc + 0] = vb.x; sB[br][bc + 1] = vb.y;
                sB[br][bc + 2] = vb.z; sB[br][bc + 3] = vb.w;
            }
            __syncthreads();
#pragma unroll
            for (int k = 0; k < 8; k++) {
                float a[8], b[8];
#pragma unroll
                for (int i = 0; i < 8; i++) a[i] = sA[k][ty * 8 + i];
#pragma unroll
                for (int j = 0; j < 8; j++) b[j] = sB[k][tx * 8 + j];
#pragma unroll
                for (int i = 0; i < 8; i++)
#pragma unroll
                    for (int j = 0; j < 8; j++)
                        acc[i][j] = fmaf(a[i], b[j], acc[i][j]);
            }
        }
    }

#pragma unroll
    for (int i = 0; i < 8; i++) {
        int m = m0 + ty * 8 + i;
        if (m < M) {
#pragma unroll
            for (int j = 0; j < 8; j++) {
                int n = tx * 8 + j;
                out[(size_t)m * 128 + n] = fmaxf(acc[i][j] + bias[n], 0.f);
            }
        }
    }
}

// ---------------- gate: gate[n] = h[n] . gate_w + gate_b ----------------
__global__ __launch_bounds__(256) void k_gate(int h_sel,
                                              const float* __restrict__ gw,
                                              const float* __restrict__ gb) {
    const float* h = buf_ptr(h_sel);
    int warp = (blockIdx.x * blockDim.x + threadIdx.x) >> 5;
    int lane = threadIdx.x & 31;
    if (warp >= NN) return;
    const float* hr = h + (size_t)warp * H;
    float sum = 0.f;
#pragma unroll
    for (int r = 0; r < 4; r++) sum += hr[lane + 32 * r] * gw[lane + 32 * r];
#pragma unroll
    for (int off = 16; off; off >>= 1) sum += __shfl_down_sync(0xffffffffu, sum, off);
    if (lane == 0) g_gate[warp] = sum + gb[0];
}

// ---------------- graph boundaries via binary search (batch is sorted) -----
__global__ void k_bounds(const void* __restrict__ batch) {
    int g = threadIdx.x;
    if (g > NG) return;
    if (g == NG) { g_gstart[NG] = NN; return; }
    int lo = 0, hi = NN;
    while (lo < hi) {
        int mid = (lo + hi) >> 1;
        if (idx_at(batch, mid) < g) lo = mid + 1; else hi = mid;
    }
    g_gstart[g] = lo;
}

// ---------------- attention pooling: one block per graph ----------------
__global__ __launch_bounds__(128) void k_pool(int h_sel) {
    const float* h = buf_ptr(h_sel);
    __shared__ float red[128];
    __shared__ float sw[128];
    int g = blockIdx.x;
    int tid = threadIdx.x;
    int s = g_gstart[g], e = g_gstart[g + 1];
    if (s == e) { g_pooled[g * H + tid] = 0.f; return; }

    // segment max of gate
    float m = -3.0e38f;
    for (int n = s + tid; n < e; n += 128) m = fmaxf(m, g_gate[n]);
    red[tid] = m;
    __syncthreads();
    for (int off = 64; off; off >>= 1) {
        if (tid < off) red[tid] = fmaxf(red[tid], red[tid + off]);
        __syncthreads();
    }
    m = red[0];
    __syncthreads();

    // denominator
    float sum = 0.f;
    for (int n = s + tid; n < e; n += 128) sum += expf(g_gate[n] - m);
    red[tid] = sum;
    __syncthreads();
    for (int off = 64; off; off >>= 1) {
        if (tid < off) red[tid] += red[tid + off];
        __syncthreads();
    }
    float den = red[0];
    __syncthreads();

    // weighted feature sum; each thread owns one column, exp computed once/node
    float acc = 0.f;
    for (int base = s; base < e; base += 128) {
        int n = base + tid;
        sw[tid] = (n < e) ? expf(g_gate[n] - m) : 0.f;
        __syncthreads();
        int cnt = min(128, e - base);
        for (int i = 0; i < cnt; i++)
            acc += sw[i] * h[(size_t)(base + i) * H + tid];
        __syncthreads();
    }
    g_pooled[g * H + tid] = acc / den;
}

// ---------------- head: relu(pooled@lin1+b1) @ lin2 + b2, log_softmax ------
__global__ __launch_bounds__(128) void k_head(
    const float* __restrict__ l1w, const float* __restrict__ l1b,
    const float* __restrict__ l2w, const float* __restrict__ l2b,
    float* __restrict__ out)
{
    __shared__ float sp[128];
    __shared__ float so[128];
    __shared__ float sl[NC];
    __shared__ float mx, ls;
    int g = blockIdx.x;
    int tid = threadIdx.x;
    sp[tid] = g_pooled[g * H + tid];
    __syncthreads();
    float o = l1b[tid];
#pragma unroll 8
    for (int k = 0; k < 128; k++) o += sp[k] * l1w[k * 128 + tid];
    so[tid] = fmaxf(o, 0.f);
    __syncthreads();
    if (tid < NC) {
        float l = l2b[tid];
#pragma unroll 8
        for (int k = 0; k < 128; k++) l += so[k] * l2w[k * NC + tid];
        sl[tid] = l;
    }
    __syncthreads();
    if (tid == 0) {
        float m = sl[0];
        for (int j = 1; j < NC; j++) m = fmaxf(m, sl[j]);
        float ssum = 0.f;
        for (int j = 0; j < NC; j++) ssum += expf(sl[j] - m);
        mx = m; ls = logf(ssum);
    }
    __syncthreads();
    if (tid < NC) out[g * NC + tid] = sl[tid] - mx - ls;
}

// ---------------- launch: pure kernel launches, no runtime API calls -------
extern "C" void kernel_launch(void* const* d_in, const int* in_sizes, int n_in,
                              void* d_out, int out_size) {
    const float* x     = (const float*)d_in[0];
    const void*  ei    = d_in[1];            // int32 or int64, probed on device
    const void*  batch = d_in[2];

    // num_graphs may or may not be materialized as a (1-element) buffer.
    // If in_sizes[3]==1 it is present and weights start at 4; else at 3.
    int wb = (n_in >= 16 && in_sizes[3] == 1) ? 4 : 3;

    const float* c1wl = (const float*)d_in[wb + 0];
    const float* c1wr = (const float*)d_in[wb + 1];
    const float* c1b  = (const float*)d_in[wb + 2];
    const float* cswl = (const float*)d_in[wb + 3];   // [2,128,128]
    const float* cswr = (const float*)d_in[wb + 4];
    const float* csb  = (const float*)d_in[wb + 5];   // [2,128]
    const float* gw   = (const float*)d_in[wb + 6];
    const float* gb   = (const float*)d_in[wb + 7];
    const float* l1w  = (const float*)d_in[wb + 8];
    const float* l1b  = (const float*)d_in[wb + 9];
    const float* l2w  = (const float*)d_in[wb + 10];
    const float* l2b  = (const float*)d_in[wb + 11];
    float* out = (float*)d_out;

    const int TB = 256;
    const int NODE_BLKS = (NN + TB - 1) / TB;          // 196
    const int EDGE_BLKS = (NE + TB - 1) / TB;          // 3125
    const int WARP_BLKS = (NN * 32 + TB - 1) / TB;     // 6250
    const int GEMM_BLKS = (NN + 127) / 128;            // 391

    // dtype probe + CSR build
    k_dtype<<<1, 32>>>(ei);
    k_zero<<<NODE_BLKS, TB>>>();
    k_count<<<EDGE_BLKS, TB>>>(ei);
    k_scan1<<<NB_SCAN, 1024>>>();
    k_scan2<<<1, 64>>>();
    k_scan3<<<NODE_BLKS, TB>>>();
    k_fill<<<EDGE_BLKS, TB>>>(ei);

    // layer 1: x -> h0
    k_agg<<<WARP_BLKS, TB>>>(x, -1);
    k_gemm<<<GEMM_BLKS, TB>>>(x, -1, c1wl, c1wr, c1b, SEL_H0, NN);
    // layer 2: h0 -> h1
    k_agg<<<WARP_BLKS, TB>>>(nullptr, SEL_H0);
    k_gemm<<<GEMM_BLKS, TB>>>(nullptr, SEL_H0, cswl, cswr, csb, SEL_H1, NN);
    // layer 3: h1 -> h0
    k_agg<<<WARP_BLKS, TB>>>(nullptr, SEL_H1);
    k_gemm<<<GEMM_BLKS, TB>>>(nullptr, SEL_H1, cswl + 128 * 128, cswr + 128 * 128,
                              csb + 128, SEL_H0, NN);

    // pooling + head
    k_gate<<<WARP_BLKS, TB>>>(SEL_H0, gw, gb);
    k_bounds<<<1, 1024>>>(batch);
    k_pool<<<NG, 128>>>(SEL_H0);
    k_head<<<NG, 128>>>(l1w, l1b, l2w, l2b, out);
}

// round 10
// speedup vs baseline: 1.0315x; 1.0315x over previous
#include <cuda_runtime.h>

#define NN 50000
#define NE 800000
#define H  128
#define NG 512
#define NC 10
#define NB_SCAN 49   // ceil(50000/1024)

// ---------------- device scratch (no allocations allowed) ----------------
__device__ int   g_deg[NN];
__device__ float g_inv[NN];
__device__ int   g_rowtmp[NN];
__device__ int   g_row[NN + 1];
__device__ int   g_cur[NN];
__device__ int   g_col[NE];
__device__ int   g_bsum[64];
__device__ int   g_boff[64];
__device__ __align__(16) float g_h0[NN * H];
__device__ __align__(16) float g_h1[NN * H];
__device__ __align__(16) float g_agg[NN * H];
__device__ float g_gate[NN];
__device__ int   g_gstart[NG + 1];
__device__ __align__(16) float g_pooled[NG * H];
__device__ int   g_i64flag;   // 1 if edge_index/batch are int64, 0 if int32

// Buffer selector resolved IN DEVICE CODE ONLY (host never touches symbols).
#define SEL_AGG 0
#define SEL_H0  1
#define SEL_H1  2
__device__ __forceinline__ float* buf_ptr(int sel) {
    return (sel == SEL_AGG) ? g_agg : (sel == SEL_H0) ? g_h0 : g_h1;
}

// dtype-dispatching index reads (probed: int32 under default JAX config)
__device__ __forceinline__ int idx_at(const void* p, long long i) {
    if (g_i64flag) return (int)((const long long*)p)[i];
    return ((const int*)p)[i];
}

// ---------------- packed f32x2 helpers (FFMA2 only reachable via PTX) ----
__device__ __forceinline__ unsigned long long pk2(float x, float y) {
    unsigned long long r;
    asm("mov.b64 %0, {%1,%2};" : "=l"(r) : "f"(x), "f"(y));
    return r;
}
__device__ __forceinline__ void upk2(unsigned long long v, float& x, float& y) {
    asm("mov.b64 {%0,%1}, %2;" : "=f"(x), "=f"(y) : "l"(v));
}
__device__ __forceinline__ void ffma2(unsigned long long& d, unsigned long long a,
                                      unsigned long long b) {
    asm("fma.rn.f32x2 %0, %1, %2, %0;" : "+l"(d) : "l"(a), "l"(b));
}

// ---------------- dtype probe: int64 data has all-zero high words ----------
__global__ void k_dtype(const void* ei) {
    const int* w = (const int*)ei;
    int t = threadIdx.x;                           // 32 threads
    long long k = (long long)t * (NE / 32) + 11;   // element index, < NE
    unsigned any = __ballot_sync(0xffffffffu, w[2 * k + 1] != 0);
    if (t == 0) g_i64flag = (any == 0) ? 1 : 0;
}

// ---------------- CSR build ----------------
__global__ void k_zero() {
    int i = blockIdx.x * blockDim.x + threadIdx.x;
    if (i < NN) { g_deg[i] = 0; g_cur[i] = 0; }
}

__global__ void k_count(const void* __restrict__ ei) {
    int e = blockIdx.x * blockDim.x + threadIdx.x;
    if (e < NE) {
        int d = idx_at(ei, (long long)NE + e);   // dst row
        if (d >= 0 && d < NN) atomicAdd(&g_deg[d], 1);
    }
}

__global__ void k_scan1() {
    __shared__ int s[1024];
    int tid = threadIdx.x;
    int i = blockIdx.x * 1024 + tid;
    int v = (i < NN) ? g_deg[i] : 0;
    s[tid] = v;
    __syncthreads();
    for (int off = 1; off < 1024; off <<= 1) {
        int t = (tid >= off) ? s[tid - off] : 0;
        __syncthreads();
        s[tid] += t;
        __syncthreads();
    }
    if (i < NN) g_rowtmp[i] = s[tid] - v;   // exclusive within block
    if (tid == 1023) g_bsum[blockIdx.x] = s[1023];
}

__global__ void k_scan2() {
    __shared__ int s[64];
    int tid = threadIdx.x;
    int v = (tid < NB_SCAN) ? g_bsum[tid] : 0;
    s[tid] = v;
    __syncthreads();
    for (int off = 1; off < 64; off <<= 1) {
        int t = (tid >= off) ? s[tid - off] : 0;
        __syncthreads();
        s[tid] += t;
        __syncthreads();
    }
    g_boff[tid] = s[tid] - v;               // exclusive block offsets
}

__global__ void k_scan3() {
    int i = blockIdx.x * blockDim.x + threadIdx.x;
    if (i < NN) {
        g_row[i] = g_rowtmp[i] + g_boff[i >> 10];
        g_inv[i] = 1.0f / fmaxf((float)g_deg[i], 1.0f);
    }
    if (i == 0) g_row[NN] = NE;
}

__global__ void k_fill(const void* __restrict__ ei) {
    int e = blockIdx.x * blockDim.x + threadIdx.x;
    if (e < NE) {
        int src = idx_at(ei, e);
        int dst = idx_at(ei, (long long)NE + e);
        if (dst >= 0 && dst < NN && src >= 0 && src < NN) {
            int pos = g_row[dst] + atomicAdd(&g_cur[dst], 1);
            g_col[pos] = src;
        }
    }
}

// ---------------- mean aggregation: warp per destination node ----------------
__global__ __launch_bounds__(256) void k_agg(const float* __restrict__ x, int in_sel) {
    const float* in = (in_sel < 0) ? x : buf_ptr(in_sel);
    int warp = (blockIdx.x * blockDim.x + threadIdx.x) >> 5;
    int lane = threadIdx.x & 31;
    if (warp >= NN) return;
    int s = g_row[warp], e = g_row[warp + 1];
    float4 acc = make_float4(0.f, 0.f, 0.f, 0.f);
    for (int i = s; i < e; i++) {
        int src = g_col[i];
        float4 v = *reinterpret_cast<const float4*>(in + (size_t)src * H + lane * 4);
        acc.x += v.x; acc.y += v.y; acc.z += v.z; acc.w += v.w;
    }
    float iv = g_inv[warp];
    acc.x *= iv; acc.y *= iv; acc.z *= iv; acc.w *= iv;
    *reinterpret_cast<float4*>(g_agg + (size_t)warp * H + lane * 4) = acc;
}

// ---------------- fused dual GEMM: out = relu(agg@W1 + A2@W2 + b) ----------------
// BM=128, BN=128, BK=8, 256 threads, 8x8 per thread, packed f32x2 FFMA2.
__global__ __launch_bounds__(256) void k_gemm(
    const float* __restrict__ x, int a2_sel,
    const float* __restrict__ W1, const float* __restrict__ W2,
    const float* __restrict__ bias, int out_sel, int M)
{
    const float* A2 = (a2_sel < 0) ? x : buf_ptr(a2_sel);
    float* out = buf_ptr(out_sel);

    __shared__ __align__(16) float sA[8][132];   // [k][m], padded; 528B row = 33*16
    __shared__ __align__(16) float sB[8][132];   // [k][n], padded
    int tid = threadIdx.x;
    int tx = tid & 15, ty = tid >> 4;
    int m0 = blockIdx.x * 128;

    unsigned long long acc[8][4];
#pragma unroll
    for (int i = 0; i < 8; i++)
#pragma unroll
        for (int j = 0; j < 4; j++) acc[i][j] = 0ULL;

    int lm = tid >> 1;            // A-load row within tile (0..127)
    int lh = (tid & 1) * 4;       // A-load col offset (0 or 4)

    for (int pass = 0; pass < 2; pass++) {
        const float* A = pass ? A2 : g_agg;
        const float* W = pass ? W2 : W1;
        for (int kc = 0; kc < 128; kc += 8) {
            float4 va = make_float4(0.f, 0.f, 0.f, 0.f);
            if (m0 + lm < M)
                va = *reinterpret_cast<const float4*>(A + (size_t)(m0 + lm) * 128 + kc + lh);
            float4 vb = *reinterpret_cast<const float4*>(W + (size_t)(kc + (tid >> 5)) * 128 + (tid & 31) * 4);
            __syncthreads();
            sA[lh + 0][lm] = va.x; sA[lh + 1][lm] = va.y;
            sA[lh + 2][lm] = va.z; sA[lh + 3][lm] = va.w;
            {
                int br = tid >> 5;            // 0..7
                int bc = (tid & 31) * 4;      // 0..124
                sB[br][bc + 0] = vb.x; sB[br][bc + 1] = vb.y;
                sB[br][bc + 2] = vb.z; sB[br][bc + 3] = vb.w;
            }
            __syncthreads();
#pragma unroll
            for (int k = 0; k < 8; k++) {
                float a[8];
#pragma unroll
                for (int i = 0; i < 8; i++) a[i] = sA[k][ty * 8 + i];
                unsigned long long bb[4];
#pragma unroll
                for (int j = 0; j < 4; j++)   // 8B-aligned: row 528B, col offset 8j B
                    bb[j] = *reinterpret_cast<const unsigned long long*>(&sB[k][tx * 8 + j * 2]);
#pragma unroll
                for (int i = 0; i < 8; i++) {
                    unsigned long long aa = pk2(a[i], a[i]);
#pragma unroll
                    for (int j = 0; j < 4; j++) ffma2(acc[i][j], aa, bb[j]);
                }
            }
        }
    }

#pragma unroll
    for (int i = 0; i < 8; i++) {
        int m = m0 + ty * 8 + i;
        if (m < M) {
#pragma unroll
            for (int j = 0; j < 4; j++) {
                int n = tx * 8 + j * 2;
                float xv, yv;
                upk2(acc[i][j], xv, yv);
                out[(size_t)m * 128 + n]     = fmaxf(xv + bias[n], 0.f);
                out[(size_t)m * 128 + n + 1] = fmaxf(yv + bias[n + 1], 0.f);
            }
        }
    }
}

// ---------------- gate: gate[n] = h[n] . gate_w + gate_b ----------------
__global__ __launch_bounds__(256) void k_gate(int h_sel,
                                              const float* __restrict__ gw,
                                              const float* __restrict__ gb) {
    const float* h = buf_ptr(h_sel);
    int warp = (blockIdx.x * blockDim.x + threadIdx.x) >> 5;
    int lane = threadIdx.x & 31;
    if (warp >= NN) return;
    const float* hr = h + (size_t)warp * H;
    float sum = 0.f;
#pragma unroll
    for (int r = 0; r < 4; r++) sum += hr[lane + 32 * r] * gw[lane + 32 * r];
#pragma unroll
    for (int off = 16; off; off >>= 1) sum += __shfl_down_sync(0xffffffffu, sum, off);
    if (lane == 0) g_gate[warp] = sum + gb[0];
}

// ---------------- graph boundaries via binary search (batch is sorted) -----
__global__ void k_bounds(const void* __restrict__ batch) {
    int g = threadIdx.x;
    if (g > NG) return;
    if (g == NG) { g_gstart[NG] = NN; return; }
    int lo = 0, hi = NN;
    while (lo < hi) {
        int mid = (lo + hi) >> 1;
        if (idx_at(batch, mid) < g) lo = mid + 1; else hi = mid;
    }
    g_gstart[g] = lo;
}

// ---------------- attention pooling: one block per graph ----------------
__global__ __launch_bounds__(128) void k_pool(int h_sel) {
    const float* h = buf_ptr(h_sel);
    __shared__ float red[128];
    __shared__ float sw[128];
    int g = blockIdx.x;
    int tid = threadIdx.x;
    int s = g_gstart[g], e = g_gstart[g + 1];
    if (s == e) { g_pooled[g * H + tid] = 0.f; return; }

    // segment max of gate
    float m = -3.0e38f;
    for (int n = s + tid; n < e; n += 128) m = fmaxf(m, g_gate[n]);
    red[tid] = m;
    __syncthreads();
    for (int off = 64; off; off >>= 1) {
        if (tid < off) red[tid] = fmaxf(red[tid], red[tid + off]);
        __syncthreads();
    }
    m = red[0];
    __syncthreads();

    // denominator
    float sum = 0.f;
    for (int n = s + tid; n < e; n += 128) sum += expf(g_gate[n] - m);
    red[tid] = sum;
    __syncthreads();
    for (int off = 64; off; off >>= 1) {
        if (tid < off) red[tid] += red[tid + off];
        __syncthreads();
    }
    float den = red[0];
    __syncthreads();

    // weighted feature sum; each thread owns one column, exp computed once/node
    float acc = 0.f;
    for (int base = s; base < e; base += 128) {
        int n = base + tid;
        sw[tid] = (n < e) ? expf(g_gate[n] - m) : 0.f;
        __syncthreads();
        int cnt = min(128, e - base);
        for (int i = 0; i < cnt; i++)
            acc += sw[i] * h[(size_t)(base + i) * H + tid];
        __syncthreads();
    }
    g_pooled[g * H + tid] = acc / den;
}

// ---------------- head: relu(pooled@lin1+b1) @ lin2 + b2, log_softmax ------
__global__ __launch_bounds__(128) void k_head(
    const float* __restrict__ l1w, const float* __restrict__ l1b,
    const float* __restrict__ l2w, const float* __restrict__ l2b,
    float* __restrict__ out)
{
    __shared__ float sp[128];
    __shared__ float so[128];
    __shared__ float sl[NC];
    __shared__ float mx, ls;
    int g = blockIdx.x;
    int tid = threadIdx.x;
    sp[tid] = g_pooled[g * H + tid];
    __syncthreads();
    float o = l1b[tid];
#pragma unroll 8
    for (int k = 0; k < 128; k++) o += sp[k] * l1w[k * 128 + tid];
    so[tid] = fmaxf(o, 0.f);
    __syncthreads();
    if (tid < NC) {
        float l = l2b[tid];
#pragma unroll 8
        for (int k = 0; k < 128; k++) l += so[k] * l2w[k * NC + tid];
        sl[tid] = l;
    }
    __syncthreads();
    if (tid == 0) {
        float m = sl[0];
        for (int j = 1; j < NC; j++) m = fmaxf(m, sl[j]);
        float ssum = 0.f;
        for (int j = 0; j < NC; j++) ssum += expf(sl[j] - m);
        mx = m; ls = logf(ssum);
    }
    __syncthreads();
    if (tid < NC) out[g * NC + tid] = sl[tid] - mx - ls;
}

// ---------------- launch: pure kernel launches, no runtime API calls -------
extern "C" void kernel_launch(void* const* d_in, const int* in_sizes, int n_in,
                              void* d_out, int out_size) {
    const float* x     = (const float*)d_in[0];
    const void*  ei    = d_in[1];            // int32 or int64, probed on device
    const void*  batch = d_in[2];

    // num_graphs may or may not be materialized as a (1-element) buffer.
    int wb = (n_in >= 16 && in_sizes[3] == 1) ? 4 : 3;

    const float* c1wl = (const float*)d_in[wb + 0];
    const float* c1wr = (const float*)d_in[wb + 1];
    const float* c1b  = (const float*)d_in[wb + 2];
    const float* cswl = (const float*)d_in[wb + 3];   // [2,128,128]
    const float* cswr = (const float*)d_in[wb + 4];
    const float* csb  = (const float*)d_in[wb + 5];   // [2,128]
    const float* gw   = (const float*)d_in[wb + 6];
    const float* gb   = (const float*)d_in[wb + 7];
    const float* l1w  = (const float*)d_in[wb + 8];
    const float* l1b  = (const float*)d_in[wb + 9];
    const float* l2w  = (const float*)d_in[wb + 10];
    const float* l2b  = (const float*)d_in[wb + 11];
    float* out = (float*)d_out;

    const int TB = 256;
    const int NODE_BLKS = (NN + TB - 1) / TB;          // 196
    const int EDGE_BLKS = (NE + TB - 1) / TB;          // 3125
    const int WARP_BLKS = (NN * 32 + TB - 1) / TB;     // 6250
    const int GEMM_BLKS = (NN + 127) / 128;            // 391

    // dtype probe + CSR build
    k_dtype<<<1, 32>>>(ei);
    k_zero<<<NODE_BLKS, TB>>>();
    k_count<<<EDGE_BLKS, TB>>>(ei);
    k_scan1<<<NB_SCAN, 1024>>>();
    k_scan2<<<1, 64>>>();
    k_scan3<<<NODE_BLKS, TB>>>();
    k_fill<<<EDGE_BLKS, TB>>>(ei);

    // layer 1: x -> h0
    k_agg<<<WARP_BLKS, TB>>>(x, -1);
    k_gemm<<<GEMM_BLKS, TB>>>(x, -1, c1wl, c1wr, c1b, SEL_H0, NN);
    // layer 2: h0 -> h1
    k_agg<<<WARP_BLKS, TB>>>(nullptr, SEL_H0);
    k_gemm<<<GEMM_BLKS, TB>>>(nullptr, SEL_H0, cswl, cswr, csb, SEL_H1, NN);
    // layer 3: h1 -> h0
    k_agg<<<WARP_BLKS, TB>>>(nullptr, SEL_H1);
    k_gemm<<<GEMM_BLKS, TB>>>(nullptr, SEL_H1, cswl + 128 * 128, cswr + 128 * 128,
                              csb + 128, SEL_H0, NN);

    // pooling + head
    k_gate<<<WARP_BLKS, TB>>>(SEL_H0, gw, gb);
    k_bounds<<<1, 1024>>>(batch);
    k_pool<<<NG, 128>>>(SEL_H0);
    k_head<<<NG, 128>>>(l1w, l1b, l2w, l2b, out);
}

// round 14
// speedup vs baseline: 1.0694x; 1.0367x over previous
#include <cuda_runtime.h>
#include <cuda_bf16.h>
#include <cstdint>

#define NN 50000
#define NE 800000
#define H  128
#define NG 512
#define NC 10
#define NB_SCAN 49   // ceil(50000/1024)

// ---------------- device scratch (no allocations allowed) ----------------
__device__ int   g_deg[NN];
__device__ float g_inv[NN];
__device__ int   g_rowtmp[NN];
__device__ int   g_row[NN + 1];
__device__ int   g_cur[NN];
__device__ int   g_col[NE];
__device__ int   g_bsum[64];
__device__ int   g_boff[64];
__device__ __align__(16) float g_h0[NN * H];
__device__ __align__(16) float g_h1[NN * H];
__device__ float g_gate[NN];
__device__ int   g_gstart[NG + 1];
__device__ __align__(16) float g_pooled[NG * H];
__device__ int   g_i64flag;

// split-bf16 operands
__device__ __align__(16) __nv_bfloat16 g_aggh[NN * H], g_aggl[NN * H];
__device__ __align__(16) __nv_bfloat16 g_xh[NN * H],   g_xl[NN * H];
__device__ __align__(16) __nv_bfloat16 g_h0h[NN * H],  g_h0l[NN * H];
__device__ __align__(16) __nv_bfloat16 g_h1h[NN * H],  g_h1l[NN * H];
// transposed split weights: [6][n*H+k]; w = 2*layer + (0=wl,1=wr)
__device__ __align__(16) __nv_bfloat16 g_wth[6][H * H], g_wtl[6][H * H];

#define SEL_H0 1
#define SEL_H1 2
__device__ __forceinline__ float* buf_ptr(int sel) {
    return (sel == SEL_H0) ? g_h0 : g_h1;
}

__device__ __forceinline__ int idx_at(const void* p, long long i) {
    if (g_i64flag) return (int)((const long long*)p)[i];
    return ((const int*)p)[i];
}

// ---------------- portable tensor-core helpers (sm_80+ PTX only) ----------
__device__ __forceinline__ uint32_t smem_u32(const void* p) {
    uint32_t a;
    asm("{ .reg .u64 t; cvta.to.shared.u64 t, %1; cvt.u32.u64 %0, t; }" : "=r"(a) : "l"(p));
    return a;
}
__device__ __forceinline__ void ldsm_x4(uint32_t& r0, uint32_t& r1, uint32_t& r2,
                                        uint32_t& r3, uint32_t addr) {
    asm volatile("ldmatrix.sync.aligned.m8n8.x4.shared.b16 {%0,%1,%2,%3}, [%4];"
                 : "=r"(r0), "=r"(r1), "=r"(r2), "=r"(r3) : "r"(addr));
}
__device__ __forceinline__ void mma_bf16(float* d, const uint32_t* a, uint32_t b0,
                                         uint32_t b1) {
    asm volatile(
        "mma.sync.aligned.m16n8k16.row.col.f32.bf16.bf16.f32 "
        "{%0,%1,%2,%3}, {%4,%5,%6,%7}, {%8,%9}, {%0,%1,%2,%3};"
        : "+f"(d[0]), "+f"(d[1]), "+f"(d[2]), "+f"(d[3])
        : "r"(a[0]), "r"(a[1]), "r"(a[2]), "r"(a[3]), "r"(b0), "r"(b1));
}

// ---------------- dtype probe ----------------
__global__ void k_dtype(const void* ei) {
    const int* w = (const int*)ei;
    int t = threadIdx.x;
    long long k = (long long)t * (NE / 32) + 11;
    unsigned any = __ballot_sync(0xffffffffu, w[2 * k + 1] != 0);
    if (t == 0) g_i64flag = (any == 0) ? 1 : 0;
}

// ---------------- weight convert: transpose + bf16 split ----------------
__global__ void k_cvtw(const float* __restrict__ c1wl, const float* __restrict__ c1wr,
                       const float* __restrict__ cswl, const float* __restrict__ cswr) {
    int w = blockIdx.y;
    int i = blockIdx.x * 256 + threadIdx.x;
    if (i >= H * H) return;
    int k = i / H, n = i % H;
    const float* src = (w == 0) ? c1wl : (w == 1) ? c1wr : (w == 2) ? cswl :
                       (w == 3) ? cswr : (w == 4) ? (cswl + H * H) : (cswr + H * H);
    float v = src[k * H + n];
    __nv_bfloat16 hv = __float2bfloat16(v);
    g_wth[w][n * H + k] = hv;
    g_wtl[w][n * H + k] = __float2bfloat16(v - __bfloat162float(hv));
}

// ---------------- x convert: bf16 split ----------------
__global__ void k_cvtx(const float* __restrict__ x) {
    int i = blockIdx.x * 256 + threadIdx.x;
    if (i >= NN * H) return;
    float v = x[i];
    __nv_bfloat16 hv = __float2bfloat16(v);
    g_xh[i] = hv;
    g_xl[i] = __float2bfloat16(v - __bfloat162float(hv));
}

// ---------------- CSR build ----------------
__global__ void k_zero() {
    int i = blockIdx.x * blockDim.x + threadIdx.x;
    if (i < NN) { g_deg[i] = 0; g_cur[i] = 0; }
}

__global__ void k_count(const void* __restrict__ ei) {
    int e = blockIdx.x * blockDim.x + threadIdx.x;
    if (e < NE) {
        int d = idx_at(ei, (long long)NE + e);
        if (d >= 0 && d < NN) atomicAdd(&g_deg[d], 1);
    }
}

__global__ void k_scan1() {
    __shared__ int s[1024];
    int tid = threadIdx.x;
    int i = blockIdx.x * 1024 + tid;
    int v = (i < NN) ? g_deg[i] : 0;
    s[tid] = v;
    __syncthreads();
    for (int off = 1; off < 1024; off <<= 1) {
        int t = (tid >= off) ? s[tid - off] : 0;
        __syncthreads();
        s[tid] += t;
        __syncthreads();
    }
    if (i < NN) g_rowtmp[i] = s[tid] - v;
    if (tid == 1023) g_bsum[blockIdx.x] = s[1023];
}

__global__ void k_scan2() {
    __shared__ int s[64];
    int tid = threadIdx.x;
    int v = (tid < NB_SCAN) ? g_bsum[tid] : 0;
    s[tid] = v;
    __syncthreads();
    for (int off = 1; off < 64; off <<= 1) {
        int t = (tid >= off) ? s[tid - off] : 0;
        __syncthreads();
        s[tid] += t;
        __syncthreads();
    }
    g_boff[tid] = s[tid] - v;
}

__global__ void k_scan3() {
    int i = blockIdx.x * blockDim.x + threadIdx.x;
    if (i < NN) {
        g_row[i] = g_rowtmp[i] + g_boff[i >> 10];
        g_inv[i] = 1.0f / fmaxf((float)g_deg[i], 1.0f);
    }
    if (i == 0) g_row[NN] = NE;
}

__global__ void k_fill(const void* __restrict__ ei) {
    int e = blockIdx.x * blockDim.x + threadIdx.x;
    if (e < NE) {
        int src = idx_at(ei, e);
        int dst = idx_at(ei, (long long)NE + e);
        if (dst >= 0 && dst < NN && src >= 0 && src < NN) {
            int pos = g_row[dst] + atomicAdd(&g_cur[dst], 1);
            g_col[pos] = src;
        }
    }
}

// ---------------- mean aggregation -> split bf16 output ----------------
__global__ __launch_bounds__(256) void k_agg(const float* __restrict__ x, int in_sel) {
    const float* in = (in_sel < 0) ? x : buf_ptr(in_sel);
    int warp = (blockIdx.x * blockDim.x + threadIdx.x) >> 5;
    int lane = threadIdx.x & 31;
    if (warp >= NN) return;
    int s = g_row[warp], e = g_row[warp + 1];
    float4 acc = make_float4(0.f, 0.f, 0.f, 0.f);
    for (int i = s; i < e; i++) {
        int src = g_col[i];
        float4 v = *reinterpret_cast<const float4*>(in + (size_t)src * H + lane * 4);
        acc.x += v.x; acc.y += v.y; acc.z += v.z; acc.w += v.w;
    }
    float iv = g_inv[warp];
    float a0 = acc.x * iv, a1 = acc.y * iv, a2 = acc.z * iv, a3 = acc.w * iv;
    size_t o = (size_t)warp * H + lane * 4;
    __nv_bfloat16 h0 = __float2bfloat16(a0), h1 = __float2bfloat16(a1);
    __nv_bfloat16 h2 = __float2bfloat16(a2), h3 = __float2bfloat16(a3);
    __nv_bfloat162 ph0(h0, h1), ph1(h2, h3);
    *reinterpret_cast<__nv_bfloat162*>(g_aggh + o)     = ph0;
    *reinterpret_cast<__nv_bfloat162*>(g_aggh + o + 2) = ph1;
    __nv_bfloat162 pl0(__float2bfloat16(a0 - __bfloat162float(h0)),
                       __float2bfloat16(a1 - __bfloat162float(h1)));
    __nv_bfloat162 pl1(__float2bfloat16(a2 - __bfloat162float(h2)),
                       __float2bfloat16(a3 - __bfloat162float(h3)));
    *reinterpret_cast<__nv_bfloat162*>(g_aggl + o)     = pl0;
    *reinterpret_cast<__nv_bfloat162*>(g_aggl + o + 2) = pl1;
}

// ---------------- HMMA dual GEMM with split-bf16 ----------------
// out = relu(agg@W_l + A2@W_r + b); 6 bf16 products into fp32 register acc.
// Block 128x128, 8 warps (4x2), warp tile 32x64 = 2x8 m16n8k16.
#define SPITCH 72   // bf16 elements per smem row (144B, odd 16B multiple)
__global__ __launch_bounds__(256) void k_tgemm(int layer, const float* __restrict__ bias)
{
    __shared__ __align__(16) __nv_bfloat16 SA[128 * SPITCH];
    __shared__ __align__(16) __nv_bfloat16 SB[128 * SPITCH];

    int tid = threadIdx.x, lane = tid & 31, wid = tid >> 5;
    int wm = wid & 3, wn = wid >> 2;       // warp grid 4x2
    int m0 = blockIdx.x * 128;

    float acc[2][8][4];
#pragma unroll
    for (int i = 0; i < 2; i++)
#pragma unroll
        for (int j = 0; j < 8; j++)
#pragma unroll
            for (int q = 0; q < 4; q++) acc[i][j][q] = 0.f;

    const __nv_bfloat16* A2h = (layer == 0) ? g_xh : (layer == 1) ? g_h0h : g_h1h;
    const __nv_bfloat16* A2l = (layer == 0) ? g_xl : (layer == 1) ? g_h0l : g_h1l;
    const __nv_bfloat16* WlH = g_wth[2 * layer], * WlL = g_wtl[2 * layer];
    const __nv_bfloat16* WrH = g_wth[2 * layer + 1], * WrL = g_wtl[2 * layer + 1];

    // 6 products; A reloaded only when source changes
    const __nv_bfloat16* alist[6] = { g_aggh, g_aggh, g_aggl, A2h, A2h, A2l };
    const __nv_bfloat16* blist[6] = { WlH, WlL, WlH, WrH, WrL, WrH };

    uint32_t sa_base = smem_u32(SA);
    uint32_t sb_base = smem_u32(SB);

    // per-lane ldmatrix addresses (byte offsets into SA/SB), k-step added later
    // A: lanes 0-15 rows, lanes 16-31 rows at +16B (k+8)
    uint32_t a_row = (uint32_t)(wm * 32 + (lane & 15));
    uint32_t a_off0 = a_row * (SPITCH * 2) + ((lane >> 4) * 16);
    // B: x4 covers two n8 tiles; lane -> n row and k-half
    uint32_t b_n = (uint32_t)(wn * 64 + ((lane >> 4) & 1) * 8 + (lane & 7));
    uint32_t b_koff = (uint32_t)(((lane >> 3) & 1) * 16);

    for (int c = 0; c < 2; c++) {          // K chunk of 64
        for (int p = 0; p < 6; p++) {
            bool loadA = (p == 0) || (alist[p] != alist[p - 1]);
            __syncthreads();               // protect smem reuse
            if (loadA) {
                const __nv_bfloat16* Asrc = alist[p];
                for (int u = tid; u < 1024; u += 256) {
                    int r = u >> 3, g16 = u & 7;
                    uint4 v = make_uint4(0, 0, 0, 0);
                    if (m0 + r < NN)
                        v = *(const uint4*)(Asrc + (size_t)(m0 + r) * H + c * 64 + g16 * 8);
                    *(uint4*)(SA + r * SPITCH + g16 * 8) = v;
                }
            }
            {
                const __nv_bfloat16* Bsrc = blist[p];
                for (int u = tid; u < 1024; u += 256) {
                    int r = u >> 3, g16 = u & 7;
                    uint4 v = *(const uint4*)(Bsrc + (size_t)r * H + c * 64 + g16 * 8);
                    *(uint4*)(SB + r * SPITCH + g16 * 8) = v;
                }
            }
            __syncthreads();
#pragma unroll
            for (int ks = 0; ks < 4; ks++) {
                uint32_t afr[2][4];
#pragma unroll
                for (int tm = 0; tm < 2; tm++) {
                    uint32_t addr = sa_base + a_off0 + (uint32_t)(tm * 16 * SPITCH * 2)
                                  + (uint32_t)(ks * 32);
                    ldsm_x4(afr[tm][0], afr[tm][1], afr[tm][2], afr[tm][3], addr);
                }
                uint32_t bfr[4][4];
#pragma unroll
                for (int g = 0; g < 4; g++) {
                    uint32_t addr = sb_base + (b_n + g * 16) * (SPITCH * 2)
                                  + b_koff + (uint32_t)(ks * 32);
                    ldsm_x4(bfr[g][0], bfr[g][1], bfr[g][2], bfr[g][3], addr);
                }
#pragma unroll
                for (int tm = 0; tm < 2; tm++)
#pragma unroll
                    for (int tn = 0; tn < 8; tn++) {
                        int g = tn >> 1, h2 = (tn & 1) * 2;
                        mma_bf16(acc[tm][tn], afr[tm], bfr[g][h2], bfr[g][h2 + 1]);
                    }
            }
        }
    }

    // epilogue: bias + relu; write fp32 h and split bf16 for next layer
    float* hout = (layer == 1) ? g_h1 : g_h0;
    __nv_bfloat16* oh = (layer == 0) ? g_h0h : g_h1h;
    __nv_bfloat16* ol = (layer == 0) ? g_h0l : g_h1l;
#pragma unroll
    for (int tm = 0; tm < 2; tm++) {
#pragma unroll
        for (int h2 = 0; h2 < 2; h2++) {
            int m = m0 + wm * 32 + tm * 16 + (lane >> 2) + h2 * 8;
            if (m >= NN) continue;
#pragma unroll
            for (int tn = 0; tn < 8; tn++) {
                int n = wn * 64 + tn * 8 + (lane & 3) * 2;
                float2 bv = *(const float2*)(bias + n);
                float v0 = fmaxf(acc[tm][tn][h2 * 2 + 0] + bv.x, 0.f);
                float v1 = fmaxf(acc[tm][tn][h2 * 2 + 1] + bv.y, 0.f);
                *(float2*)(hout + (size_t)m * H + n) = make_float2(v0, v1);
                if (layer < 2) {
                    __nv_bfloat16 hv0 = __float2bfloat16(v0);
                    __nv_bfloat16 hv1 = __float2bfloat16(v1);
                    *(__nv_bfloat162*)(oh + (size_t)m * H + n) = __nv_bfloat162(hv0, hv1);
                    *(__nv_bfloat162*)(ol + (size_t)m * H + n) =
                        __nv_bfloat162(__float2bfloat16(v0 - __bfloat162float(hv0)),
                                       __float2bfloat16(v1 - __bfloat162float(hv1)));
                }
            }
        }
    }
}

// ---------------- gate ----------------
__global__ __launch_bounds__(256) void k_gate(int h_sel,
                                              const float* __restrict__ gw,
                                              const float* __restrict__ gb) {
    const float* h = buf_ptr(h_sel);
    int warp = (blockIdx.x * blockDim.x + threadIdx.x) >> 5;
    int lane = threadIdx.x & 31;
    if (warp >= NN) return;
    const float* hr = h + (size_t)warp * H;
    float sum = 0.f;
#pragma unroll
    for (int r = 0; r < 4; r++) sum += hr[lane + 32 * r] * gw[lane + 32 * r];
#pragma unroll
    for (int off = 16; off; off >>= 1) sum += __shfl_down_sync(0xffffffffu, sum, off);
    if (lane == 0) g_gate[warp] = sum + gb[0];
}

// ---------------- graph boundaries ----------------
__global__ void k_bounds(const void* __restrict__ batch) {
    int g = threadIdx.x;
    if (g > NG) return;
    if (g == NG) { g_gstart[NG] = NN; return; }
    int lo = 0, hi = NN;
    while (lo < hi) {
        int mid = (lo + hi) >> 1;
        if (idx_at(batch, mid) < g) lo = mid + 1; else hi = mid;
    }
    g_gstart[g] = lo;
}

// ---------------- attention pooling ----------------
__global__ __launch_bounds__(128) void k_pool(int h_sel) {
    const float* h = buf_ptr(h_sel);
    __shared__ float red[128];
    __shared__ float sw[128];
    int g = blockIdx.x;
    int tid = threadIdx.x;
    int s = g_gstart[g], e = g_gstart[g + 1];
    if (s == e) { g_pooled[g * H + tid] = 0.f; return; }

    float m = -3.0e38f;
    for (int n = s + tid; n < e; n += 128) m = fmaxf(m, g_gate[n]);
    red[tid] = m;
    __syncthreads();
    for (int off = 64; off; off >>= 1) {
        if (tid < off) red[tid] = fmaxf(red[tid], red[tid + off]);
        __syncthreads();
    }
    m = red[0];
    __syncthreads();

    float sum = 0.f;
    for (int n = s + tid; n < e; n += 128) sum += expf(g_gate[n] - m);
    red[tid] = sum;
    __syncthreads();
    for (int off = 64; off; off >>= 1) {
        if (tid < off) red[tid] += red[tid + off];
        __syncthreads();
    }
    float den = red[0];
    __syncthreads();

    float acc = 0.f;
    for (int base = s; base < e; base += 128) {
        int n = base + tid;
        sw[tid] = (n < e) ? expf(g_gate[n] - m) : 0.f;
        __syncthreads();
        int cnt = min(128, e - base);
        for (int i = 0; i < cnt; i++)
            acc += sw[i] * h[(size_t)(base + i) * H + tid];
        __syncthreads();
    }
    g_pooled[g * H + tid] = acc / den;
}

// ---------------- head ----------------
__global__ __launch_bounds__(128) void k_head(
    const float* __restrict__ l1w, const float* __restrict__ l1b,
    const float* __restrict__ l2w, const float* __restrict__ l2b,
    float* __restrict__ out)
{
    __shared__ float sp[128];
    __shared__ float so[128];
    __shared__ float sl[NC];
    __shared__ float mx, ls;
    int g = blockIdx.x;
    int tid = threadIdx.x;
    sp[tid] = g_pooled[g * H + tid];
    __syncthreads();
    float o = l1b[tid];
#pragma unroll 8
    for (int k = 0; k < 128; k++) o += sp[k] * l1w[k * 128 + tid];
    so[tid] = fmaxf(o, 0.f);
    __syncthreads();
    if (tid < NC) {
        float l = l2b[tid];
#pragma unroll 8
        for (int k = 0; k < 128; k++) l += so[k] * l2w[k * NC + tid];
        sl[tid] = l;
    }
    __syncthreads();
    if (tid == 0) {
        float m = sl[0];
        for (int j = 1; j < NC; j++) m = fmaxf(m, sl[j]);
        float ssum = 0.f;
        for (int j = 0; j < NC; j++) ssum += expf(sl[j] - m);
        mx = m; ls = logf(ssum);
    }
    __syncthreads();
    if (tid < NC) out[g * NC + tid] = sl[tid] - mx - ls;
}

// ---------------- launch ----------------
extern "C" void kernel_launch(void* const* d_in, const int* in_sizes, int n_in,
                              void* d_out, int out_size) {
    const float* x     = (const float*)d_in[0];
    const void*  ei    = d_in[1];
    const void*  batch = d_in[2];

    int wb = (n_in >= 16 && in_sizes[3] == 1) ? 4 : 3;

    const float* c1wl = (const float*)d_in[wb + 0];
    const float* c1wr = (const float*)d_in[wb + 1];
    const float* c1b  = (const float*)d_in[wb + 2];
    const float* cswl = (const float*)d_in[wb + 3];
    const float* cswr = (const float*)d_in[wb + 4];
    const float* csb  = (const float*)d_in[wb + 5];
    const float* gw   = (const float*)d_in[wb + 6];
    const float* gb   = (const float*)d_in[wb + 7];
    const float* l1w  = (const float*)d_in[wb + 8];
    const float* l1b  = (const float*)d_in[wb + 9];
    const float* l2w  = (const float*)d_in[wb + 10];
    const float* l2b  = (const float*)d_in[wb + 11];
    float* out = (float*)d_out;

    const int TB = 256;
    const int NODE_BLKS = (NN + TB - 1) / TB;
    const int EDGE_BLKS = (NE + TB - 1) / TB;
    const int WARP_BLKS = (NN * 32 + TB - 1) / TB;
    const int TILE_BLKS = (NN + 127) / 128;          // 391

    // probe + operand prep + CSR build
    k_dtype<<<1, 32>>>(ei);
    k_cvtw<<<dim3((H * H + 255) / 256, 6), 256>>>(c1wl, c1wr, cswl, cswr);
    k_cvtx<<<(NN * H + 255) / 256, 256>>>(x);
    k_zero<<<NODE_BLKS, TB>>>();
    k_count<<<EDGE_BLKS, TB>>>(ei);
    k_scan1<<<NB_SCAN, 1024>>>();
    k_scan2<<<1, 64>>>();
    k_scan3<<<NODE_BLKS, TB>>>();
    k_fill<<<EDGE_BLKS, TB>>>(ei);

    // layer 1: agg(x) ; h0 = relu(agg@W1l + x@W1r + b1)
    k_agg<<<WARP_BLKS, TB>>>(x, -1);
    k_tgemm<<<TILE_BLKS, 256>>>(0, c1b);
    // layer 2
    k_agg<<<WARP_BLKS, TB>>>(nullptr, SEL_H0);
    k_tgemm<<<TILE_BLKS, 256>>>(1, csb);
    // layer 3
    k_agg<<<WARP_BLKS, TB>>>(nullptr, SEL_H1);
    k_tgemm<<<TILE_BLKS, 256>>>(2, csb + H);

    // pooling + head
    k_gate<<<WARP_BLKS, TB>>>(SEL_H0, gw, gb);
    k_bounds<<<1, 1024>>>(batch);
    k_pool<<<NG, 128>>>(SEL_H0);
    k_head<<<NG, 128>>>(l1w, l1b, l2w, l2b, out);
}